// round 13
// baseline (speedup 1.0000x reference)
#include <cuda_runtime.h>
#include <cuda_fp16.h>
#include <cstdint>

#define NA    100000
#define NEDGE 200000
#define HID   512
#define AD    133
#define BD    14
#define KIN   147   // AD + BD
#define KOUT  645   // AD + HID
#define KP1   160   // KIN padded to 32
#define KP2   512
#define KP3   672   // KOUT padded to 32
#define CK    32    // K chunk (gather modes)

// ---------------- scratch (static device globals; no allocation) ------------
__device__ float g_h0 [(size_t)NEDGE * HID];
__device__ float g_hA [(size_t)NEDGE * HID];
__device__ float g_hB [(size_t)NEDGE * HID];
__device__ float g_agg[(size_t)NA    * HID];
// dense fp16 message operand
__device__ __align__(16) unsigned short g_mF[(size_t)NEDGE * HID];
// fp16 weights, K-padded
__device__ __align__(16) unsigned short g_WiF[512 * KP1];
__device__ __align__(16) unsigned short g_WhF[512 * KP2];
__device__ __align__(16) unsigned short g_WoF[512 * KP3];

// ---------------- helpers ----------------------------------------------------
__device__ __forceinline__ uint32_t smem_u32(const void* p) {
    uint32_t a;
    asm("{ .reg .u64 t; cvta.to.shared.u64 t, %1; cvt.u32.u64 %0, t; }" : "=r"(a) : "l"(p));
    return a;
}
__device__ __forceinline__ void ldsm4(uint32_t* r, uint32_t addr) {
    asm volatile("ldmatrix.sync.aligned.m8n8.x4.shared.b16 {%0,%1,%2,%3}, [%4];"
                 : "=r"(r[0]), "=r"(r[1]), "=r"(r[2]), "=r"(r[3]) : "r"(addr));
}
__device__ __forceinline__ void mma16816(float* d, const uint32_t* a,
                                         uint32_t b0, uint32_t b1) {
    asm volatile(
        "mma.sync.aligned.m16n8k16.row.col.f32.f16.f16.f32 "
        "{%0,%1,%2,%3}, {%4,%5,%6,%7}, {%8,%9}, {%0,%1,%2,%3};"
        : "+f"(d[0]), "+f"(d[1]), "+f"(d[2]), "+f"(d[3])
        : "r"(a[0]), "r"(a[1]), "r"(a[2]), "r"(a[3]), "r"(b0), "r"(b1));
}
__device__ __forceinline__ void cp16(uint32_t dst, const void* src) {
    asm volatile("cp.async.ca.shared.global [%0], [%1], 16;" :: "r"(dst), "l"(src));
}
// pack 8 fp32 -> 8 fp16 (RNE) in one uint4
__device__ __forceinline__ uint4 pack8h(const float* x) {
    uint4 r;
    __half2 p0 = __floats2half2_rn(x[0], x[1]);
    __half2 p1 = __floats2half2_rn(x[2], x[3]);
    __half2 p2 = __floats2half2_rn(x[4], x[5]);
    __half2 p3 = __floats2half2_rn(x[6], x[7]);
    r.x = *(uint32_t*)&p0; r.y = *(uint32_t*)&p1;
    r.z = *(uint32_t*)&p2; r.w = *(uint32_t*)&p3;
    return r;
}

// ---------------- utility kernels ------------------------------------------
__global__ void cvtw_k(const float* __restrict__ W,
                       unsigned short* __restrict__ out,
                       int N, int K, int Kp) {
    int idx = blockIdx.x * blockDim.x + threadIdx.x;
    if (idx >= N * Kp) return;
    int n = idx / Kp, k = idx - n * Kp;
    float v = (k < K) ? W[(size_t)n * K + k] : 0.f;
    __half h = __float2half_rn(v);
    out[idx] = *(unsigned short*)&h;
}

__global__ void zero_k(float4* __restrict__ p, int n4) {
    int i = blockIdx.x * blockDim.x + threadIdx.x;
    if (i < n4) p[i] = make_float4(0.f, 0.f, 0.f, 0.f);
}

__global__ void scatter_k(const float* __restrict__ h,
                          const int* __restrict__ dst,
                          const float* __restrict__ wgt,
                          float* __restrict__ agg) {
    int idx = blockIdx.x * blockDim.x + threadIdx.x;
    if (idx >= NEDGE * 128) return;
    int e = idx >> 7;
    int c = (idx & 127) << 2;
    int d = dst[e];
    float w = wgt ? wgt[e] : 1.0f;
    float4 hv = *(const float4*)(h + (size_t)e * HID + c);
    float* a = agg + (size_t)d * HID + c;
    atomicAdd(a + 0, w * hv.x);
    atomicAdd(a + 1, w * hv.y);
    atomicAdd(a + 2, w * hv.z);
    atomicAdd(a + 3, w * hv.w);
}

// message formation: m_e = agg[src[e]] - wgt[rev[e]] * h[rev[e]], fp16 out
__global__ void msg_k(const float* __restrict__ h,
                      const int* __restrict__ src,
                      const int* __restrict__ rev,
                      const float* __restrict__ wgt,
                      const float* __restrict__ agg,
                      unsigned short* __restrict__ mF) {
    int idx = blockIdx.x * blockDim.x + threadIdx.x;   // NEDGE * 64 threads
    if (idx >= NEDGE * 64) return;
    int e = idx >> 6;
    int c = (idx & 63) << 3;
    int s = src[e];
    int r = rev[e];
    float w = wgt[r];
    const float* ap = agg + (size_t)s * HID + c;
    const float* hp = h   + (size_t)r * HID + c;
    float4 a0 = *(const float4*)ap;
    float4 a1 = *(const float4*)(ap + 4);
    float4 h0 = *(const float4*)hp;
    float4 h1 = *(const float4*)(hp + 4);
    float x[8] = { a0.x - w * h0.x, a0.y - w * h0.y, a0.z - w * h0.z, a0.w - w * h0.w,
                   a1.x - w * h1.x, a1.y - w * h1.y, a1.z - w * h1.z, a1.w - w * h1.w };
    *(uint4*)(mF + (size_t)e * HID + c) = pack8h(x);
}

__global__ void batch_k(const int* __restrict__ b, float* __restrict__ out) {
    int i = blockIdx.x * blockDim.x + threadIdx.x;
    if (i < NA) out[i] = (float)b[i];
}

#define SW(o) ((o) ^ (((o) >> 3) & 0x70))

// ---------------- dense fp16 GEMM (message step) -----------------------------
// C[M,512] = relu( A @ W^T + h0 ).  CTA 128x128, K=512 fixed, CK=64 full rows,
// 3-stage cp.async ring, 256 thr, 2 CTAs/SM, warp tile 64x32.
#define DST   32768                    // stage stride (A 16KB + B 16KB)
#define SMEM_DENSE (3 * DST)           // 98304

__global__ __launch_bounds__(256, 2)
void gemm_dense(const unsigned short* __restrict__ AF,
                const unsigned short* __restrict__ WF,
                const float* __restrict__ h0,
                float* __restrict__ C)
{
    extern __shared__ __align__(1024) char sm[];
    const uint32_t sb = smem_u32(sm);
    const int tid   = threadIdx.x;
    const int lane  = tid & 31;
    const int warp  = tid >> 5;
    const int warpM = warp >> 2;        // 0..1
    const int warpN = warp & 3;         // 0..3

    const int jb = blockIdx.x * 128;
    const int mb = blockIdx.y * 128;

    // loader: 2 threads/row, each 64B (32 fp16)
    const int arow = tid >> 1;
    const int aq   = tid & 1;

    float acc[4][4][4];
#pragma unroll
    for (int i = 0; i < 4; i++)
#pragma unroll
        for (int n = 0; n < 4; n++)
#pragma unroll
            for (int k = 0; k < 4; k++) acc[i][n][k] = 0.f;

#define CPT(kb, base) do {                                                      \
    const unsigned short* aF = AF + (size_t)(mb + arow) * KP2 + (kb) + aq * 32; \
    const unsigned short* wF = WF + (size_t)(jb + arow) * KP2 + (kb) + aq * 32; \
    int o = arow * 128 + aq * 64;                                               \
    cp16(sb + (base) + SW(o),           aF);                                    \
    cp16(sb + (base) + SW(o + 16),      aF + 8);                                \
    cp16(sb + (base) + SW(o + 32),      aF + 16);                               \
    cp16(sb + (base) + SW(o + 48),      aF + 24);                               \
    cp16(sb + (base) + 16384 + SW(o),      wF);                                 \
    cp16(sb + (base) + 16384 + SW(o + 16), wF + 8);                             \
    cp16(sb + (base) + 16384 + SW(o + 32), wF + 16);                            \
    cp16(sb + (base) + 16384 + SW(o + 48), wF + 24);                            \
    asm volatile("cp.async.commit_group;" ::: "memory");                        \
} while (0)

#define DOMMA64(base) do {                                                      \
    _Pragma("unroll")                                                           \
    for (int s = 0; s < 4; s++) {                                               \
        const int cb = s * 32 + ((lane >> 4) << 4);                             \
        uint32_t Bf[2][4];                                                      \
        _Pragma("unroll")                                                       \
        for (int j = 0; j < 2; j++) {                                           \
            int r = warpN * 32 + j * 16 + (lane & 15);                          \
            ldsm4(Bf[j], sb + (base) + 16384 + SW(r * 128 + cb));               \
        }                                                                       \
        _Pragma("unroll")                                                       \
        for (int i = 0; i < 4; i++) {                                           \
            uint32_t Af[4];                                                     \
            int r = warpM * 64 + i * 16 + (lane & 15);                          \
            ldsm4(Af, sb + (base) + SW(r * 128 + cb));                          \
            _Pragma("unroll")                                                   \
            for (int nt = 0; nt < 4; nt++) {                                    \
                int j = nt >> 1, sel = nt & 1;                                  \
                mma16816(acc[i][nt], Af, Bf[j][sel], Bf[j][sel + 2]);           \
            }                                                                   \
        }                                                                       \
    }                                                                           \
} while (0)

    const int nc = KP2 / 64;            // 8
    CPT(0,  0 * DST);
    CPT(64, 1 * DST);
    for (int t = 0; t < nc; t++) {
        asm volatile("cp.async.wait_group 1;" ::: "memory");
        __syncthreads();
        if (t + 2 < nc) CPT((t + 2) * 64, ((t + 2) % 3) * DST);
        DOMMA64((t % 3) * DST);
    }
#undef CPT
#undef DOMMA64

    // epilogue: + h0, relu
#pragma unroll
    for (int i = 0; i < 4; i++)
#pragma unroll
        for (int nt = 0; nt < 4; nt++) {
            const int r0 = mb + warpM * 64 + i * 16 + (lane >> 2);
            const int c  = jb + warpN * 32 + nt * 8 + (lane & 3) * 2;
#pragma unroll
            for (int hh2 = 0; hh2 < 2; hh2++) {
                const int r = r0 + hh2 * 8;
                const size_t base = (size_t)r * HID + c;
                float2 a = *(const float2*)(h0 + base);
                float2 o;
                o.x = fmaxf(acc[i][nt][hh2 * 2 + 0] + a.x, 0.f);
                o.y = fmaxf(acc[i][nt][hh2 * 2 + 1] + a.y, 0.f);
                *(float2*)(C + base) = o;
            }
        }
}

// ---------------- gather-mode fp16 GEMM (modes 1 and 3) ----------------------
// Same as R12: CK=32, 2-stage, fused gather A, cp.async B.
#define SMEM_GEMM 65536

template <int MODE>
__global__ __launch_bounds__(256, 2)
void gemm_mma(const unsigned short* __restrict__ WF,
              const float* __restrict__ Vf,
              const float* __restrict__ Eb,
              const int* __restrict__ src,
              const float* __restrict__ agg,
              const float* __restrict__ bias,
              float* __restrict__ C,
              int M, int K, int Kp)
{
    extern __shared__ __align__(1024) char sm[];
    const uint32_t sb = smem_u32(sm);
    const int tid   = threadIdx.x;
    const int lane  = tid & 31;
    const int warp  = tid >> 5;
    const int warpM = warp >> 2;
    const int warpN = warp & 3;

    const int jb = blockIdx.x * 128;
    const int mb = blockIdx.y * 128;

    const int arow  = tid >> 1;
    const int aq    = tid & 1;
    const int agrow = mb + arow;
    const bool aok  = (agrow < M);

    int sidx = 0;
    if (MODE == 1) { if (aok) sidx = src[agrow]; }

    float acc[4][4][4];
#pragma unroll
    for (int i = 0; i < 4; i++)
#pragma unroll
        for (int n = 0; n < 4; n++)
#pragma unroll
            for (int k = 0; k < 4; k++) acc[i][n][k] = 0.f;

    float ar[16];

#define GLOAD_A(kb) do {                                                        \
    _Pragma("unroll")                                                           \
    for (int i = 0; i < 16; i++) {                                              \
        int kk = (kb) + aq * 16 + i; float v = 0.f;                             \
        if (MODE == 1) {                                                        \
            if (aok && kk < KIN)                                                \
                v = (kk < AD) ? Vf[(size_t)sidx * AD + kk]                      \
                              : Eb[(size_t)agrow * BD + (kk - AD)];             \
        } else {                                                                \
            if (aok && kk < KOUT)                                               \
                v = (kk < AD) ? Vf[(size_t)agrow * AD + kk]                     \
                              : agg[(size_t)agrow * HID + (kk - AD)];           \
        }                                                                       \
        ar[i] = v;                                                              \
    }                                                                           \
} while (0)

#define CPTILE(kb, base) do {                                                   \
    const unsigned short* sF = WF + (size_t)(jb + arow) * Kp + (kb) + aq * 16;  \
    int ob = arow * 128 + aq * 32;                                              \
    cp16(sb + (base) + 16384 + SW(ob),      sF);                                \
    cp16(sb + (base) + 16384 + SW(ob + 16), sF + 8);                            \
    asm volatile("cp.async.commit_group;" ::: "memory");                        \
} while (0)

#define SSTORE_A(base) do {                                                     \
    int oa = arow * 128 + aq * 32;                                              \
    *(uint4*)(sm + (base) + SW(oa))      = pack8h(ar);                          \
    *(uint4*)(sm + (base) + SW(oa + 16)) = pack8h(ar + 8);                      \
} while (0)

#define DOMMA(base) do {                                                        \
    _Pragma("unroll")                                                           \
    for (int s = 0; s < 2; s++) {                                               \
        const int cb = s * 32 + ((lane >> 4) << 4);                             \
        uint32_t Bf[2][4];                                                      \
        _Pragma("unroll")                                                       \
        for (int j = 0; j < 2; j++) {                                           \
            int r = warpN * 32 + j * 16 + (lane & 15);                          \
            ldsm4(Bf[j], sb + (base) + 16384 + SW(r * 128 + cb));               \
        }                                                                       \
        _Pragma("unroll")                                                       \
        for (int i = 0; i < 4; i++) {                                           \
            uint32_t Af[4];                                                     \
            int r = warpM * 64 + i * 16 + (lane & 15);                          \
            ldsm4(Af, sb + (base) + SW(r * 128 + cb));                          \
            _Pragma("unroll")                                                   \
            for (int nt = 0; nt < 4; nt++) {                                    \
                int j = nt >> 1, sel = nt & 1;                                  \
                mma16816(acc[i][nt], Af, Bf[j][sel], Bf[j][sel + 2]);           \
            }                                                                   \
        }                                                                       \
    }                                                                           \
} while (0)

    const int nc = (K + CK - 1) / CK;
    GLOAD_A(0);
    CPTILE(0, 0);
    SSTORE_A(0);
    asm volatile("cp.async.wait_group 0;" ::: "memory");
    __syncthreads();

    for (int t = 0; t < nc; t++) {
        const int base  = (t & 1) * 32768;
        const int obase = 32768 - base;
        const bool nxt = (t + 1 < nc);
        if (nxt) { GLOAD_A((t + 1) * CK); CPTILE((t + 1) * CK, obase); }
        DOMMA(base);
        if (nxt) {
            SSTORE_A(obase);
            asm volatile("cp.async.wait_group 0;" ::: "memory");
            __syncthreads();
        }
    }
#undef GLOAD_A
#undef CPTILE
#undef SSTORE_A
#undef DOMMA

    // epilogue
#pragma unroll
    for (int i = 0; i < 4; i++)
#pragma unroll
        for (int nt = 0; nt < 4; nt++) {
            const int r0 = mb + warpM * 64 + i * 16 + (lane >> 2);
            const int c  = jb + warpN * 32 + nt * 8 + (lane & 3) * 2;
#pragma unroll
            for (int hh2 = 0; hh2 < 2; hh2++) {
                const int r = r0 + hh2 * 8;
                if (r < M) {
                    float v0 = acc[i][nt][hh2 * 2 + 0];
                    float v1 = acc[i][nt][hh2 * 2 + 1];
                    const size_t base = (size_t)r * HID + c;
                    if (MODE == 3) { v0 += bias[c]; v1 += bias[c + 1]; }
                    float2 o;
                    o.x = fmaxf(v0, 0.f);
                    o.y = fmaxf(v1, 0.f);
                    *(float2*)(C + base) = o;
                }
            }
        }
}

// ---------------- driver -----------------------------------------------------
extern "C" void kernel_launch(void* const* d_in, const int* in_sizes, int n_in,
                              void* d_out, int out_size)
{
    const float* V     = (const float*)d_in[0];
    const float* E     = (const float*)d_in[1];
    const int*   eidx  = (const int*)d_in[2];
    const int*   rev   = (const int*)d_in[3];
    const int*   batch = (const int*)d_in[4];
    const float* wgt   = (const float*)d_in[5];
    const float* W_i   = (const float*)d_in[6];
    const float* W_h   = (const float*)d_in[7];
    const float* W_o   = (const float*)d_in[8];
    const float* b_o   = (const float*)d_in[9];

    const int* src = eidx;
    const int* dst = eidx + NEDGE;
    float* out = (float*)d_out;

    float *h0, *hA, *hB, *agg;
    cudaGetSymbolAddress((void**)&h0,  g_h0);
    cudaGetSymbolAddress((void**)&hA,  g_hA);
    cudaGetSymbolAddress((void**)&hB,  g_hB);
    cudaGetSymbolAddress((void**)&agg, g_agg);
    unsigned short *mF, *WiF, *WhF, *WoF;
    cudaGetSymbolAddress((void**)&mF,  g_mF);
    cudaGetSymbolAddress((void**)&WiF, g_WiF);
    cudaGetSymbolAddress((void**)&WhF, g_WhF);
    cudaGetSymbolAddress((void**)&WoF, g_WoF);

    cudaFuncSetAttribute(gemm_dense,  cudaFuncAttributeMaxDynamicSharedMemorySize, SMEM_DENSE);
    cudaFuncSetAttribute(gemm_mma<1>, cudaFuncAttributeMaxDynamicSharedMemorySize, SMEM_GEMM);
    cudaFuncSetAttribute(gemm_mma<3>, cudaFuncAttributeMaxDynamicSharedMemorySize, SMEM_GEMM);

    const dim3 blk(256);
    const dim3 grid_e(4, (NEDGE + 127) / 128);
    const dim3 grid_a(4, (NA    + 127) / 128);
    const int  aggN4    = (NA * HID) / 4;
    const int  zeroGrid = (aggN4 + 255) / 256;
    const int  scatGrid = (NEDGE * 128 + 255) / 256;
    const int  msgGrid  = (NEDGE * 64  + 255) / 256;

    float* hOut = out + (size_t)NA * HID + NA;

    // 0) convert weights to fp16 (K-padded)
    cvtw_k<<<(512 * KP1 + 255) / 256, 256>>>(W_i, WiF, 512, KIN,  KP1);
    cvtw_k<<<(512 * KP2 + 255) / 256, 256>>>(W_h, WhF, 512, HID,  KP2);
    cvtw_k<<<(512 * KP3 + 255) / 256, 256>>>(W_o, WoF, 512, KOUT, KP3);

    // 1) h0 = relu([V[src];E] @ W_i^T)
    gemm_mma<1><<<grid_e, blk, SMEM_GEMM>>>(WiF, V, E, src, nullptr, nullptr,
                                            h0, NEDGE, KIN, KP1);

    // 2) three message-passing steps; last writes h into d_out
    const float* hin = h0;
    float* houts[3] = { hA, hB, hOut };
    for (int t = 0; t < 3; t++) {
        zero_k<<<zeroGrid, 256>>>((float4*)agg, aggN4);
        scatter_k<<<scatGrid, 256>>>(hin, dst, wgt, agg);
        msg_k<<<msgGrid, 256>>>(hin, src, rev, wgt, agg, mF);
        gemm_dense<<<grid_e, blk, SMEM_DENSE>>>(mF, WhF, h0, houts[t]);
        hin = houts[t];
    }
    float* hFinal = hOut;

    // 3) final aggregation (unweighted)
    zero_k<<<zeroGrid, 256>>>((float4*)agg, aggN4);
    scatter_k<<<scatGrid, 256>>>(hFinal, dst, nullptr, agg);

    // 4) h_atom = relu([V;agg] @ W_o^T + b_o)
    gemm_mma<3><<<grid_a, blk, SMEM_GEMM>>>(WoF, V, nullptr, nullptr, agg, b_o,
                                            out, NA, KOUT, KP3);

    // 5) atom_batch as float
    batch_k<<<(NA + 255) / 256, 256>>>(batch, out + (size_t)NA * HID);
}

// round 14
// speedup vs baseline: 1.1270x; 1.1270x over previous
#include <cuda_runtime.h>
#include <cuda_fp16.h>
#include <cstdint>

#define NA    100000
#define NEDGE 200000
#define HID   512
#define AD    133
#define BD    14
#define KIN   147   // AD + BD
#define KOUT  645   // AD + HID
#define KP1   160   // KIN padded to 32
#define KP2   512
#define KP3   672   // KOUT padded to 32
#define CK    32    // K chunk

// ---------------- scratch (static device globals; no allocation) ------------
__device__ float g_h0 [(size_t)NEDGE * HID];        // fp32 residual
__device__ float g_agg[(size_t)NA    * HID];
__device__ __align__(16) unsigned short g_h16[(size_t)NEDGE * HID];  // fp16 h
__device__ __align__(16) unsigned short g_mF [(size_t)NEDGE * HID];  // fp16 msg
// fp16 weights, K-padded
__device__ __align__(16) unsigned short g_WiF[512 * KP1];
__device__ __align__(16) unsigned short g_WhF[512 * KP2];
__device__ __align__(16) unsigned short g_WoF[512 * KP3];

// ---------------- helpers ----------------------------------------------------
__device__ __forceinline__ uint32_t smem_u32(const void* p) {
    uint32_t a;
    asm("{ .reg .u64 t; cvta.to.shared.u64 t, %1; cvt.u32.u64 %0, t; }" : "=r"(a) : "l"(p));
    return a;
}
__device__ __forceinline__ void ldsm4(uint32_t* r, uint32_t addr) {
    asm volatile("ldmatrix.sync.aligned.m8n8.x4.shared.b16 {%0,%1,%2,%3}, [%4];"
                 : "=r"(r[0]), "=r"(r[1]), "=r"(r[2]), "=r"(r[3]) : "r"(addr));
}
__device__ __forceinline__ void mma16816(float* d, const uint32_t* a,
                                         uint32_t b0, uint32_t b1) {
    asm volatile(
        "mma.sync.aligned.m16n8k16.row.col.f32.f16.f16.f32 "
        "{%0,%1,%2,%3}, {%4,%5,%6,%7}, {%8,%9}, {%0,%1,%2,%3};"
        : "+f"(d[0]), "+f"(d[1]), "+f"(d[2]), "+f"(d[3])
        : "r"(a[0]), "r"(a[1]), "r"(a[2]), "r"(a[3]), "r"(b0), "r"(b1));
}
__device__ __forceinline__ void cp16(uint32_t dst, const void* src) {
    asm volatile("cp.async.ca.shared.global [%0], [%1], 16;" :: "r"(dst), "l"(src));
}
__device__ __forceinline__ void red4(float* p, float a, float b, float c, float d) {
    asm volatile("red.global.add.v4.f32 [%0], {%1,%2,%3,%4};"
                 :: "l"(p), "f"(a), "f"(b), "f"(c), "f"(d) : "memory");
}
// pack 8 fp32 -> 8 fp16 (RNE) in one uint4
__device__ __forceinline__ uint4 pack8h(const float* x) {
    uint4 r;
    __half2 p0 = __floats2half2_rn(x[0], x[1]);
    __half2 p1 = __floats2half2_rn(x[2], x[3]);
    __half2 p2 = __floats2half2_rn(x[4], x[5]);
    __half2 p3 = __floats2half2_rn(x[6], x[7]);
    r.x = *(uint32_t*)&p0; r.y = *(uint32_t*)&p1;
    r.z = *(uint32_t*)&p2; r.w = *(uint32_t*)&p3;
    return r;
}
// unpack uint4 (8 fp16) -> 8 fp32
__device__ __forceinline__ void unpack8h(uint4 v, float* x) {
    __half2* ph = (__half2*)&v;
#pragma unroll
    for (int i = 0; i < 4; i++) {
        float2 f = __half22float2(ph[i]);
        x[i * 2 + 0] = f.x;
        x[i * 2 + 1] = f.y;
    }
}

// ---------------- utility kernels ------------------------------------------
__global__ void cvtw_k(const float* __restrict__ W,
                       unsigned short* __restrict__ out,
                       int N, int K, int Kp) {
    int idx = blockIdx.x * blockDim.x + threadIdx.x;
    if (idx >= N * Kp) return;
    int n = idx / Kp, k = idx - n * Kp;
    float v = (k < K) ? W[(size_t)n * K + k] : 0.f;
    __half h = __float2half_rn(v);
    out[idx] = *(unsigned short*)&h;
}

__global__ void zero_k(float4* __restrict__ p, int n4) {
    int i = blockIdx.x * blockDim.x + threadIdx.x;
    if (i < n4) p[i] = make_float4(0.f, 0.f, 0.f, 0.f);
}

// agg[dst[e]] += w[e] * h16[e]  (fp16 input, v4 reductions)
__global__ void scatter_k(const unsigned short* __restrict__ h16,
                          const int* __restrict__ dst,
                          const float* __restrict__ wgt,
                          float* __restrict__ agg) {
    int idx = blockIdx.x * blockDim.x + threadIdx.x;   // NEDGE * 64 threads
    if (idx >= NEDGE * 64) return;
    int e = idx >> 6;
    int c = (idx & 63) << 3;
    int d = dst[e];
    float w = wgt ? wgt[e] : 1.0f;
    uint4 hv = *(const uint4*)(h16 + (size_t)e * HID + c);
    float x[8];
    unpack8h(hv, x);
    float* a = agg + (size_t)d * HID + c;
    red4(a,     w * x[0], w * x[1], w * x[2], w * x[3]);
    red4(a + 4, w * x[4], w * x[5], w * x[6], w * x[7]);
}

// m_e = agg[src[e]] - wgt[rev[e]] * h16[rev[e]], fp16 out
__global__ void msg_k(const unsigned short* __restrict__ h16,
                      const int* __restrict__ src,
                      const int* __restrict__ rev,
                      const float* __restrict__ wgt,
                      const float* __restrict__ agg,
                      unsigned short* __restrict__ mF) {
    int idx = blockIdx.x * blockDim.x + threadIdx.x;   // NEDGE * 64 threads
    if (idx >= NEDGE * 64) return;
    int e = idx >> 6;
    int c = (idx & 63) << 3;
    int s = src[e];
    int r = rev[e];
    float w = wgt[r];
    const float* ap = agg + (size_t)s * HID + c;
    float4 a0 = *(const float4*)ap;
    float4 a1 = *(const float4*)(ap + 4);
    uint4 hv = *(const uint4*)(h16 + (size_t)r * HID + c);
    float h[8];
    unpack8h(hv, h);
    float x[8] = { a0.x - w * h[0], a0.y - w * h[1], a0.z - w * h[2], a0.w - w * h[3],
                   a1.x - w * h[4], a1.y - w * h[5], a1.z - w * h[6], a1.w - w * h[7] };
    *(uint4*)(mF + (size_t)e * HID + c) = pack8h(x);
}

__global__ void batch_k(const int* __restrict__ b, float* __restrict__ out) {
    int i = blockIdx.x * blockDim.x + threadIdx.x;
    if (i < NA) out[i] = (float)b[i];
}

#define SW(o) ((o) ^ (((o) >> 3) & 0x70))

// ---------------- dense fp16 GEMM (message step) -----------------------------
// relu( A @ W^T + h0 ) -> C16 (fp16) always; C32 (fp32) if non-null.
// CTA 128x128, CK=32, 2-stage, 256 thr, 2 CTAs/SM, warp tile 64x32.
#define SMEM_GEMM 65536

__global__ __launch_bounds__(256, 2)
void gemm_dense(const unsigned short* __restrict__ AF,
                const unsigned short* __restrict__ WF,
                const float* __restrict__ h0,
                float* __restrict__ C32,
                unsigned short* __restrict__ C16)
{
    extern __shared__ __align__(1024) char sm[];
    const uint32_t sb = smem_u32(sm);
    const int tid   = threadIdx.x;
    const int lane  = tid & 31;
    const int warp  = tid >> 5;
    const int warpM = warp >> 2;
    const int warpN = warp & 3;

    const int jb = blockIdx.x * 128;
    const int mb = blockIdx.y * 128;

    const int arow = tid >> 1;
    const int aq   = tid & 1;

    float acc[4][4][4];
#pragma unroll
    for (int i = 0; i < 4; i++)
#pragma unroll
        for (int n = 0; n < 4; n++)
#pragma unroll
            for (int k = 0; k < 4; k++) acc[i][n][k] = 0.f;

#define CPT(kb, base) do {                                                      \
    const unsigned short* aF = AF + (size_t)(mb + arow) * KP2 + (kb) + aq * 16; \
    const unsigned short* wF = WF + (size_t)(jb + arow) * KP2 + (kb) + aq * 16; \
    int o = arow * 128 + aq * 32;                                               \
    cp16(sb + (base) + SW(o),      aF);                                         \
    cp16(sb + (base) + SW(o + 16), aF + 8);                                     \
    cp16(sb + (base) + 16384 + SW(o),      wF);                                 \
    cp16(sb + (base) + 16384 + SW(o + 16), wF + 8);                             \
    asm volatile("cp.async.commit_group;" ::: "memory");                        \
} while (0)

#define DOMMA(base) do {                                                        \
    _Pragma("unroll")                                                           \
    for (int s = 0; s < 2; s++) {                                               \
        const int cb = s * 32 + ((lane >> 4) << 4);                             \
        uint32_t Bf[2][4];                                                      \
        _Pragma("unroll")                                                       \
        for (int j = 0; j < 2; j++) {                                           \
            int r = warpN * 32 + j * 16 + (lane & 15);                          \
            ldsm4(Bf[j], sb + (base) + 16384 + SW(r * 128 + cb));               \
        }                                                                       \
        _Pragma("unroll")                                                       \
        for (int i = 0; i < 4; i++) {                                           \
            uint32_t Af[4];                                                     \
            int r = warpM * 64 + i * 16 + (lane & 15);                          \
            ldsm4(Af, sb + (base) + SW(r * 128 + cb));                          \
            _Pragma("unroll")                                                   \
            for (int nt = 0; nt < 4; nt++) {                                    \
                int j = nt >> 1, sel = nt & 1;                                  \
                mma16816(acc[i][nt], Af, Bf[j][sel], Bf[j][sel + 2]);           \
            }                                                                   \
        }                                                                       \
    }                                                                           \
} while (0)

    const int nc = KP2 / CK;            // 16
    CPT(0, 0);
    asm volatile("cp.async.wait_group 0;" ::: "memory");
    __syncthreads();
    for (int t = 0; t < nc; t++) {
        const int base  = (t & 1) * 32768;
        const int obase = 32768 - base;
        const bool nxt = (t + 1 < nc);
        if (nxt) CPT((t + 1) * CK, obase);
        DOMMA(base);
        if (nxt) {
            asm volatile("cp.async.wait_group 0;" ::: "memory");
            __syncthreads();
        }
    }
#undef CPT
#undef DOMMA

    // epilogue: + h0, relu -> fp16 (and fp32 if C32)
#pragma unroll
    for (int i = 0; i < 4; i++)
#pragma unroll
        for (int nt = 0; nt < 4; nt++) {
            const int r0 = mb + warpM * 64 + i * 16 + (lane >> 2);
            const int c  = jb + warpN * 32 + nt * 8 + (lane & 3) * 2;
#pragma unroll
            for (int hh2 = 0; hh2 < 2; hh2++) {
                const int r = r0 + hh2 * 8;
                const size_t base = (size_t)r * HID + c;
                float2 a = *(const float2*)(h0 + base);
                float2 o;
                o.x = fmaxf(acc[i][nt][hh2 * 2 + 0] + a.x, 0.f);
                o.y = fmaxf(acc[i][nt][hh2 * 2 + 1] + a.y, 0.f);
                if (C32) *(float2*)(C32 + base) = o;
                __half2 p = __floats2half2_rn(o.x, o.y);
                *(uint32_t*)(C16 + base) = *(uint32_t*)&p;
            }
        }
}

// ---------------- gather-mode fp16 GEMM (modes 1 and 3) ----------------------
// MODE 1: A row e = [V[src[e]];E[e]], K=147 -> C32 (h0) + C16 (h16)
// MODE 3: A row i = [V[i];agg[i]],    K=645, +bias -> C32 only
template <int MODE>
__global__ __launch_bounds__(256, 2)
void gemm_mma(const unsigned short* __restrict__ WF,
              const float* __restrict__ Vf,
              const float* __restrict__ Eb,
              const int* __restrict__ src,
              const float* __restrict__ agg,
              const float* __restrict__ bias,
              float* __restrict__ C32,
              unsigned short* __restrict__ C16,
              int M, int K, int Kp)
{
    extern __shared__ __align__(1024) char sm[];
    const uint32_t sb = smem_u32(sm);
    const int tid   = threadIdx.x;
    const int lane  = tid & 31;
    const int warp  = tid >> 5;
    const int warpM = warp >> 2;
    const int warpN = warp & 3;

    const int jb = blockIdx.x * 128;
    const int mb = blockIdx.y * 128;

    const int arow  = tid >> 1;
    const int aq    = tid & 1;
    const int agrow = mb + arow;
    const bool aok  = (agrow < M);

    int sidx = 0;
    if (MODE == 1) { if (aok) sidx = src[agrow]; }

    float acc[4][4][4];
#pragma unroll
    for (int i = 0; i < 4; i++)
#pragma unroll
        for (int n = 0; n < 4; n++)
#pragma unroll
            for (int k = 0; k < 4; k++) acc[i][n][k] = 0.f;

    float ar[16];

#define GLOAD_A(kb) do {                                                        \
    _Pragma("unroll")                                                           \
    for (int i = 0; i < 16; i++) {                                              \
        int kk = (kb) + aq * 16 + i; float v = 0.f;                             \
        if (MODE == 1) {                                                        \
            if (aok && kk < KIN)                                                \
                v = (kk < AD) ? Vf[(size_t)sidx * AD + kk]                      \
                              : Eb[(size_t)agrow * BD + (kk - AD)];             \
        } else {                                                                \
            if (aok && kk < KOUT)                                               \
                v = (kk < AD) ? Vf[(size_t)agrow * AD + kk]                     \
                              : agg[(size_t)agrow * HID + (kk - AD)];           \
        }                                                                       \
        ar[i] = v;                                                              \
    }                                                                           \
} while (0)

#define CPTILE(kb, base) do {                                                   \
    const unsigned short* sF = WF + (size_t)(jb + arow) * Kp + (kb) + aq * 16;  \
    int ob = arow * 128 + aq * 32;                                              \
    cp16(sb + (base) + 16384 + SW(ob),      sF);                                \
    cp16(sb + (base) + 16384 + SW(ob + 16), sF + 8);                            \
    asm volatile("cp.async.commit_group;" ::: "memory");                        \
} while (0)

#define SSTORE_A(base) do {                                                     \
    int oa = arow * 128 + aq * 32;                                              \
    *(uint4*)(sm + (base) + SW(oa))      = pack8h(ar);                          \
    *(uint4*)(sm + (base) + SW(oa + 16)) = pack8h(ar + 8);                      \
} while (0)

#define DOMMA(base) do {                                                        \
    _Pragma("unroll")                                                           \
    for (int s = 0; s < 2; s++) {                                               \
        const int cb = s * 32 + ((lane >> 4) << 4);                             \
        uint32_t Bf[2][4];                                                      \
        _Pragma("unroll")                                                       \
        for (int j = 0; j < 2; j++) {                                           \
            int r = warpN * 32 + j * 16 + (lane & 15);                          \
            ldsm4(Bf[j], sb + (base) + 16384 + SW(r * 128 + cb));               \
        }                                                                       \
        _Pragma("unroll")                                                       \
        for (int i = 0; i < 4; i++) {                                           \
            uint32_t Af[4];                                                     \
            int r = warpM * 64 + i * 16 + (lane & 15);                          \
            ldsm4(Af, sb + (base) + SW(r * 128 + cb));                          \
            _Pragma("unroll")                                                   \
            for (int nt = 0; nt < 4; nt++) {                                    \
                int j = nt >> 1, sel = nt & 1;                                  \
                mma16816(acc[i][nt], Af, Bf[j][sel], Bf[j][sel + 2]);           \
            }                                                                   \
        }                                                                       \
    }                                                                           \
} while (0)

    const int nc = (K + CK - 1) / CK;
    GLOAD_A(0);
    CPTILE(0, 0);
    SSTORE_A(0);
    asm volatile("cp.async.wait_group 0;" ::: "memory");
    __syncthreads();

    for (int t = 0; t < nc; t++) {
        const int base  = (t & 1) * 32768;
        const int obase = 32768 - base;
        const bool nxt = (t + 1 < nc);
        if (nxt) { GLOAD_A((t + 1) * CK); CPTILE((t + 1) * CK, obase); }
        DOMMA(base);
        if (nxt) {
            SSTORE_A(obase);
            asm volatile("cp.async.wait_group 0;" ::: "memory");
            __syncthreads();
        }
    }
#undef GLOAD_A
#undef CPTILE
#undef SSTORE_A
#undef DOMMA

    // epilogue
#pragma unroll
    for (int i = 0; i < 4; i++)
#pragma unroll
        for (int nt = 0; nt < 4; nt++) {
            const int r0 = mb + warpM * 64 + i * 16 + (lane >> 2);
            const int c  = jb + warpN * 32 + nt * 8 + (lane & 3) * 2;
#pragma unroll
            for (int hh2 = 0; hh2 < 2; hh2++) {
                const int r = r0 + hh2 * 8;
                if (r < M) {
                    float v0 = acc[i][nt][hh2 * 2 + 0];
                    float v1 = acc[i][nt][hh2 * 2 + 1];
                    const size_t base = (size_t)r * HID + c;
                    if (MODE == 3) { v0 += bias[c]; v1 += bias[c + 1]; }
                    float2 o;
                    o.x = fmaxf(v0, 0.f);
                    o.y = fmaxf(v1, 0.f);
                    *(float2*)(C32 + base) = o;
                    if (MODE == 1) {
                        __half2 p = __floats2half2_rn(o.x, o.y);
                        *(uint32_t*)(C16 + base) = *(uint32_t*)&p;
                    }
                }
            }
        }
}

// ---------------- driver -----------------------------------------------------
extern "C" void kernel_launch(void* const* d_in, const int* in_sizes, int n_in,
                              void* d_out, int out_size)
{
    const float* V     = (const float*)d_in[0];
    const float* E     = (const float*)d_in[1];
    const int*   eidx  = (const int*)d_in[2];
    const int*   rev   = (const int*)d_in[3];
    const int*   batch = (const int*)d_in[4];
    const float* wgt   = (const float*)d_in[5];
    const float* W_i   = (const float*)d_in[6];
    const float* W_h   = (const float*)d_in[7];
    const float* W_o   = (const float*)d_in[8];
    const float* b_o   = (const float*)d_in[9];

    const int* src = eidx;
    const int* dst = eidx + NEDGE;
    float* out = (float*)d_out;

    float *h0, *agg;
    cudaGetSymbolAddress((void**)&h0,  g_h0);
    cudaGetSymbolAddress((void**)&agg, g_agg);
    unsigned short *h16, *mF, *WiF, *WhF, *WoF;
    cudaGetSymbolAddress((void**)&h16, g_h16);
    cudaGetSymbolAddress((void**)&mF,  g_mF);
    cudaGetSymbolAddress((void**)&WiF, g_WiF);
    cudaGetSymbolAddress((void**)&WhF, g_WhF);
    cudaGetSymbolAddress((void**)&WoF, g_WoF);

    cudaFuncSetAttribute(gemm_dense,  cudaFuncAttributeMaxDynamicSharedMemorySize, SMEM_GEMM);
    cudaFuncSetAttribute(gemm_mma<1>, cudaFuncAttributeMaxDynamicSharedMemorySize, SMEM_GEMM);
    cudaFuncSetAttribute(gemm_mma<3>, cudaFuncAttributeMaxDynamicSharedMemorySize, SMEM_GEMM);

    const dim3 blk(256);
    const dim3 grid_e(4, (NEDGE + 127) / 128);
    const dim3 grid_a(4, (NA    + 127) / 128);
    const int  aggN4    = (NA * HID) / 4;
    const int  zeroGrid = (aggN4 + 255) / 256;
    const int  ewGrid   = (NEDGE * 64 + 255) / 256;

    float* hOut = out + (size_t)NA * HID + NA;

    // 0) convert weights to fp16 (K-padded)
    cvtw_k<<<(512 * KP1 + 255) / 256, 256>>>(W_i, WiF, 512, KIN,  KP1);
    cvtw_k<<<(512 * KP2 + 255) / 256, 256>>>(W_h, WhF, 512, HID,  KP2);
    cvtw_k<<<(512 * KP3 + 255) / 256, 256>>>(W_o, WoF, 512, KOUT, KP3);

    // 1) h0 = relu([V[src];E] @ W_i^T)  -> fp32 h0 + fp16 h16
    gemm_mma<1><<<grid_e, blk, SMEM_GEMM>>>(WiF, V, E, src, nullptr, nullptr,
                                            h0, h16, NEDGE, KIN, KP1);

    // 2) three message-passing steps; fp16 h in flight; last also writes fp32 h
    for (int t = 0; t < 3; t++) {
        zero_k<<<zeroGrid, 256>>>((float4*)agg, aggN4);
        scatter_k<<<ewGrid, 256>>>(h16, dst, wgt, agg);
        msg_k<<<ewGrid, 256>>>(h16, src, rev, wgt, agg, mF);
        gemm_dense<<<grid_e, blk, SMEM_GEMM>>>(mF, WhF, h0,
                                               (t == 2) ? hOut : nullptr, h16);
    }

    // 3) final aggregation (unweighted) from fp16 h
    zero_k<<<zeroGrid, 256>>>((float4*)agg, aggN4);
    scatter_k<<<ewGrid, 256>>>(h16, dst, nullptr, agg);

    // 4) h_atom = relu([V;agg] @ W_o^T + b_o)
    gemm_mma<3><<<grid_a, blk, SMEM_GEMM>>>(WoF, V, nullptr, nullptr, agg, b_o,
                                            out, nullptr, NA, KOUT, KP3);

    // 5) atom_batch as float
    batch_k<<<(NA + 255) / 256, 256>>>(batch, out + (size_t)NA * HID);
}

// round 15
// speedup vs baseline: 1.1339x; 1.0062x over previous
#include <cuda_runtime.h>
#include <cuda_fp16.h>
#include <cstdint>

#define NA    100000
#define NEDGE 200000
#define HID   512
#define AD    133
#define BD    14
#define KIN   147   // AD + BD
#define KOUT  645   // AD + HID
#define KP1   160   // KIN padded to 32
#define KP2   512
#define KP3   672   // KOUT padded to 32
#define CK    32    // K chunk

// ---------------- scratch (static device globals; no allocation) ------------
__device__ float g_h0 [(size_t)NEDGE * HID];        // fp32 residual
__device__ float g_agg[(size_t)NA    * HID];
__device__ __align__(16) unsigned short g_h16[(size_t)NEDGE * HID];  // fp16 h
__device__ __align__(16) unsigned short g_mF [(size_t)NEDGE * HID];  // fp16 msg
// fp16 weights, K-padded
__device__ __align__(16) unsigned short g_WiF[512 * KP1];
__device__ __align__(16) unsigned short g_WhF[512 * KP2];
__device__ __align__(16) unsigned short g_WoF[512 * KP3];

// ---------------- helpers ----------------------------------------------------
__device__ __forceinline__ uint32_t smem_u32(const void* p) {
    uint32_t a;
    asm("{ .reg .u64 t; cvta.to.shared.u64 t, %1; cvt.u32.u64 %0, t; }" : "=r"(a) : "l"(p));
    return a;
}
__device__ __forceinline__ void ldsm4(uint32_t* r, uint32_t addr) {
    asm volatile("ldmatrix.sync.aligned.m8n8.x4.shared.b16 {%0,%1,%2,%3}, [%4];"
                 : "=r"(r[0]), "=r"(r[1]), "=r"(r[2]), "=r"(r[3]) : "r"(addr));
}
__device__ __forceinline__ void mma16816(float* d, const uint32_t* a,
                                         uint32_t b0, uint32_t b1) {
    asm volatile(
        "mma.sync.aligned.m16n8k16.row.col.f32.f16.f16.f32 "
        "{%0,%1,%2,%3}, {%4,%5,%6,%7}, {%8,%9}, {%0,%1,%2,%3};"
        : "+f"(d[0]), "+f"(d[1]), "+f"(d[2]), "+f"(d[3])
        : "r"(a[0]), "r"(a[1]), "r"(a[2]), "r"(a[3]), "r"(b0), "r"(b1));
}
__device__ __forceinline__ void cp16(uint32_t dst, const void* src) {
    asm volatile("cp.async.ca.shared.global [%0], [%1], 16;" :: "r"(dst), "l"(src));
}
__device__ __forceinline__ void red4(float* p, float a, float b, float c, float d) {
    asm volatile("red.global.add.v4.f32 [%0], {%1,%2,%3,%4};"
                 :: "l"(p), "f"(a), "f"(b), "f"(c), "f"(d) : "memory");
}
// pack 8 fp32 -> 8 fp16 (RNE) in one uint4
__device__ __forceinline__ uint4 pack8h(const float* x) {
    uint4 r;
    __half2 p0 = __floats2half2_rn(x[0], x[1]);
    __half2 p1 = __floats2half2_rn(x[2], x[3]);
    __half2 p2 = __floats2half2_rn(x[4], x[5]);
    __half2 p3 = __floats2half2_rn(x[6], x[7]);
    r.x = *(uint32_t*)&p0; r.y = *(uint32_t*)&p1;
    r.z = *(uint32_t*)&p2; r.w = *(uint32_t*)&p3;
    return r;
}
// unpack uint4 (8 fp16) -> 8 fp32
__device__ __forceinline__ void unpack8h(uint4 v, float* x) {
    __half2* ph = (__half2*)&v;
#pragma unroll
    for (int i = 0; i < 4; i++) {
        float2 f = __half22float2(ph[i]);
        x[i * 2 + 0] = f.x;
        x[i * 2 + 1] = f.y;
    }
}

// ---------------- utility kernels ------------------------------------------
__global__ void cvtw_k(const float* __restrict__ W,
                       unsigned short* __restrict__ out,
                       int N, int K, int Kp) {
    int idx = blockIdx.x * blockDim.x + threadIdx.x;
    if (idx >= N * Kp) return;
    int n = idx / Kp, k = idx - n * Kp;
    float v = (k < K) ? W[(size_t)n * K + k] : 0.f;
    __half h = __float2half_rn(v);
    out[idx] = *(unsigned short*)&h;
}

__global__ void zero_k(float4* __restrict__ p, int n4) {
    int i = blockIdx.x * blockDim.x + threadIdx.x;
    if (i < n4) p[i] = make_float4(0.f, 0.f, 0.f, 0.f);
}

// agg[dst[e]] += w[e] * h16[e]  (fp16 input, v4 reductions)
__global__ void scatter_k(const unsigned short* __restrict__ h16,
                          const int* __restrict__ dst,
                          const float* __restrict__ wgt,
                          float* __restrict__ agg) {
    int idx = blockIdx.x * blockDim.x + threadIdx.x;   // NEDGE * 64 threads
    if (idx >= NEDGE * 64) return;
    int e = idx >> 6;
    int c = (idx & 63) << 3;
    int d = dst[e];
    float w = wgt ? wgt[e] : 1.0f;
    uint4 hv = *(const uint4*)(h16 + (size_t)e * HID + c);
    float x[8];
    unpack8h(hv, x);
    float* a = agg + (size_t)d * HID + c;
    red4(a,     w * x[0], w * x[1], w * x[2], w * x[3]);
    red4(a + 4, w * x[4], w * x[5], w * x[6], w * x[7]);
}

// m_e = agg[src[e]] - wgt[rev[e]] * h16[rev[e]], fp16 out
__global__ void msg_k(const unsigned short* __restrict__ h16,
                      const int* __restrict__ src,
                      const int* __restrict__ rev,
                      const float* __restrict__ wgt,
                      const float* __restrict__ agg,
                      unsigned short* __restrict__ mF) {
    int idx = blockIdx.x * blockDim.x + threadIdx.x;   // NEDGE * 64 threads
    if (idx >= NEDGE * 64) return;
    int e = idx >> 6;
    int c = (idx & 63) << 3;
    int s = src[e];
    int r = rev[e];
    float w = wgt[r];
    const float* ap = agg + (size_t)s * HID + c;
    float4 a0 = *(const float4*)ap;
    float4 a1 = *(const float4*)(ap + 4);
    uint4 hv = *(const uint4*)(h16 + (size_t)r * HID + c);
    float h[8];
    unpack8h(hv, h);
    float x[8] = { a0.x - w * h[0], a0.y - w * h[1], a0.z - w * h[2], a0.w - w * h[3],
                   a1.x - w * h[4], a1.y - w * h[5], a1.z - w * h[6], a1.w - w * h[7] };
    *(uint4*)(mF + (size_t)e * HID + c) = pack8h(x);
}

__global__ void batch_k(const int* __restrict__ b, float* __restrict__ out) {
    int i = blockIdx.x * blockDim.x + threadIdx.x;
    if (i < NA) out[i] = (float)b[i];
}

#define SW(o) ((o) ^ (((o) >> 3) & 0x70))

// ---------------- dense fp16 GEMM (message step) -----------------------------
// relu( A @ W^T + h0 ) -> C16 (fp16) always; C32 (fp32) if non-null.
// CTA 128x128, CK=32, 2-stage, 256 thr, 2 CTAs/SM, warp tile 64x32.
#define SMEM_GEMM 65536

__global__ __launch_bounds__(256, 2)
void gemm_dense(const unsigned short* __restrict__ AF,
                const unsigned short* __restrict__ WF,
                const float* __restrict__ h0,
                float* __restrict__ C32,
                unsigned short* __restrict__ C16)
{
    extern __shared__ __align__(1024) char sm[];
    const uint32_t sb = smem_u32(sm);
    const int tid   = threadIdx.x;
    const int lane  = tid & 31;
    const int warp  = tid >> 5;
    const int warpM = warp >> 2;
    const int warpN = warp & 3;

    const int jb = blockIdx.x * 128;
    const int mb = blockIdx.y * 128;

    const int arow = tid >> 1;
    const int aq   = tid & 1;

    float acc[4][4][4];
#pragma unroll
    for (int i = 0; i < 4; i++)
#pragma unroll
        for (int n = 0; n < 4; n++)
#pragma unroll
            for (int k = 0; k < 4; k++) acc[i][n][k] = 0.f;

#define CPT(kb, base) do {                                                      \
    const unsigned short* aF = AF + (size_t)(mb + arow) * KP2 + (kb) + aq * 16; \
    const unsigned short* wF = WF + (size_t)(jb + arow) * KP2 + (kb) + aq * 16; \
    int o = arow * 128 + aq * 32;                                               \
    cp16(sb + (base) + SW(o),      aF);                                         \
    cp16(sb + (base) + SW(o + 16), aF + 8);                                     \
    cp16(sb + (base) + 16384 + SW(o),      wF);                                 \
    cp16(sb + (base) + 16384 + SW(o + 16), wF + 8);                             \
    asm volatile("cp.async.commit_group;" ::: "memory");                        \
} while (0)

#define DOMMA(base) do {                                                        \
    _Pragma("unroll")                                                           \
    for (int s = 0; s < 2; s++) {                                               \
        const int cb = s * 32 + ((lane >> 4) << 4);                             \
        uint32_t Bf[2][4];                                                      \
        _Pragma("unroll")                                                       \
        for (int j = 0; j < 2; j++) {                                           \
            int r = warpN * 32 + j * 16 + (lane & 15);                          \
            ldsm4(Bf[j], sb + (base) + 16384 + SW(r * 128 + cb));               \
        }                                                                       \
        _Pragma("unroll")                                                       \
        for (int i = 0; i < 4; i++) {                                           \
            uint32_t Af[4];                                                     \
            int r = warpM * 64 + i * 16 + (lane & 15);                          \
            ldsm4(Af, sb + (base) + SW(r * 128 + cb));                          \
            _Pragma("unroll")                                                   \
            for (int nt = 0; nt < 4; nt++) {                                    \
                int j = nt >> 1, sel = nt & 1;                                  \
                mma16816(acc[i][nt], Af, Bf[j][sel], Bf[j][sel + 2]);           \
            }                                                                   \
        }                                                                       \
    }                                                                           \
} while (0)

    const int nc = KP2 / CK;            // 16
    CPT(0, 0);
    asm volatile("cp.async.wait_group 0;" ::: "memory");
    __syncthreads();
    for (int t = 0; t < nc; t++) {
        const int base  = (t & 1) * 32768;
        const int obase = 32768 - base;
        const bool nxt = (t + 1 < nc);
        if (nxt) CPT((t + 1) * CK, obase);
        DOMMA(base);
        if (nxt) {
            asm volatile("cp.async.wait_group 0;" ::: "memory");
            __syncthreads();
        }
    }
#undef CPT
#undef DOMMA

    // epilogue: + h0, relu -> fp16 (and fp32 if C32)
#pragma unroll
    for (int i = 0; i < 4; i++)
#pragma unroll
        for (int nt = 0; nt < 4; nt++) {
            const int r0 = mb + warpM * 64 + i * 16 + (lane >> 2);
            const int c  = jb + warpN * 32 + nt * 8 + (lane & 3) * 2;
#pragma unroll
            for (int hh2 = 0; hh2 < 2; hh2++) {
                const int r = r0 + hh2 * 8;
                const size_t base = (size_t)r * HID + c;
                float2 a = *(const float2*)(h0 + base);
                float2 o;
                o.x = fmaxf(acc[i][nt][hh2 * 2 + 0] + a.x, 0.f);
                o.y = fmaxf(acc[i][nt][hh2 * 2 + 1] + a.y, 0.f);
                if (C32) *(float2*)(C32 + base) = o;
                __half2 p = __floats2half2_rn(o.x, o.y);
                *(uint32_t*)(C16 + base) = *(uint32_t*)&p;
            }
        }
}

// ---------------- gather-mode fp16 GEMM (modes 1 and 3) ----------------------
// MODE 1: A row e = [V[src[e]];E[e]], K=147 -> C32 (h0) + C16 (h16)
// MODE 3: A row i = [V[i];agg[i]],    K=645, +bias -> C32 only
template <int MODE>
__global__ __launch_bounds__(256, 2)
void gemm_mma(const unsigned short* __restrict__ WF,
              const float* __restrict__ Vf,
              const float* __restrict__ Eb,
              const int* __restrict__ src,
              const float* __restrict__ agg,
              const float* __restrict__ bias,
              float* __restrict__ C32,
              unsigned short* __restrict__ C16,
              int M, int K, int Kp)
{
    extern __shared__ __align__(1024) char sm[];
    const uint32_t sb = smem_u32(sm);
    const int tid   = threadIdx.x;
    const int lane  = tid & 31;
    const int warp  = tid >> 5;
    const int warpM = warp >> 2;
    const int warpN = warp & 3;

    const int jb = blockIdx.x * 128;
    const int mb = blockIdx.y * 128;

    const int arow  = tid >> 1;
    const int aq    = tid & 1;
    const int agrow = mb + arow;
    const bool aok  = (agrow < M);

    int sidx = 0;
    if (MODE == 1) { if (aok) sidx = src[agrow]; }

    float acc[4][4][4];
#pragma unroll
    for (int i = 0; i < 4; i++)
#pragma unroll
        for (int n = 0; n < 4; n++)
#pragma unroll
            for (int k = 0; k < 4; k++) acc[i][n][k] = 0.f;

    float ar[16];

#define GLOAD_A(kb) do {                                                        \
    _Pragma("unroll")                                                           \
    for (int i = 0; i < 16; i++) {                                              \
        int kk = (kb) + aq * 16 + i; float v = 0.f;                             \
        if (MODE == 1) {                                                        \
            if (aok && kk < KIN)                                                \
                v = (kk < AD) ? Vf[(size_t)sidx * AD + kk]                      \
                              : Eb[(size_t)agrow * BD + (kk - AD)];             \
        } else {                                                                \
            if (aok && kk < KOUT)                                               \
                v = (kk < AD) ? Vf[(size_t)agrow * AD + kk]                     \
                              : agg[(size_t)agrow * HID + (kk - AD)];           \
        }                                                                       \
        ar[i] = v;                                                              \
    }                                                                           \
} while (0)

#define CPTILE(kb, base) do {                                                   \
    const unsigned short* sF = WF + (size_t)(jb + arow) * Kp + (kb) + aq * 16;  \
    int ob = arow * 128 + aq * 32;                                              \
    cp16(sb + (base) + 16384 + SW(ob),      sF);                                \
    cp16(sb + (base) + 16384 + SW(ob + 16), sF + 8);                            \
    asm volatile("cp.async.commit_group;" ::: "memory");                        \
} while (0)

#define SSTORE_A(base) do {                                                     \
    int oa = arow * 128 + aq * 32;                                              \
    *(uint4*)(sm + (base) + SW(oa))      = pack8h(ar);                          \
    *(uint4*)(sm + (base) + SW(oa + 16)) = pack8h(ar + 8);                      \
} while (0)

#define DOMMA(base) do {                                                        \
    _Pragma("unroll")                                                           \
    for (int s = 0; s < 2; s++) {                                               \
        const int cb = s * 32 + ((lane >> 4) << 4);                             \
        uint32_t Bf[2][4];                                                      \
        _Pragma("unroll")                                                       \
        for (int j = 0; j < 2; j++) {                                           \
            int r = warpN * 32 + j * 16 + (lane & 15);                          \
            ldsm4(Bf[j], sb + (base) + 16384 + SW(r * 128 + cb));               \
        }                                                                       \
        _Pragma("unroll")                                                       \
        for (int i = 0; i < 4; i++) {                                           \
            uint32_t Af[4];                                                     \
            int r = warpM * 64 + i * 16 + (lane & 15);                          \
            ldsm4(Af, sb + (base) + SW(r * 128 + cb));                          \
            _Pragma("unroll")                                                   \
            for (int nt = 0; nt < 4; nt++) {                                    \
                int j = nt >> 1, sel = nt & 1;                                  \
                mma16816(acc[i][nt], Af, Bf[j][sel], Bf[j][sel + 2]);           \
            }                                                                   \
        }                                                                       \
    }                                                                           \
} while (0)

    const int nc = (K + CK - 1) / CK;
    GLOAD_A(0);
    CPTILE(0, 0);
    SSTORE_A(0);
    asm volatile("cp.async.wait_group 0;" ::: "memory");
    __syncthreads();

    for (int t = 0; t < nc; t++) {
        const int base  = (t & 1) * 32768;
        const int obase = 32768 - base;
        const bool nxt = (t + 1 < nc);
        if (nxt) { GLOAD_A((t + 1) * CK); CPTILE((t + 1) * CK, obase); }
        DOMMA(base);
        if (nxt) {
            SSTORE_A(obase);
            asm volatile("cp.async.wait_group 0;" ::: "memory");
            __syncthreads();
        }
    }
#undef GLOAD_A
#undef CPTILE
#undef SSTORE_A
#undef DOMMA

    // epilogue
#pragma unroll
    for (int i = 0; i < 4; i++)
#pragma unroll
        for (int nt = 0; nt < 4; nt++) {
            const int r0 = mb + warpM * 64 + i * 16 + (lane >> 2);
            const int c  = jb + warpN * 32 + nt * 8 + (lane & 3) * 2;
#pragma unroll
            for (int hh2 = 0; hh2 < 2; hh2++) {
                const int r = r0 + hh2 * 8;
                if (r < M) {
                    float v0 = acc[i][nt][hh2 * 2 + 0];
                    float v1 = acc[i][nt][hh2 * 2 + 1];
                    const size_t base = (size_t)r * HID + c;
                    if (MODE == 3) { v0 += bias[c]; v1 += bias[c + 1]; }
                    float2 o;
                    o.x = fmaxf(v0, 0.f);
                    o.y = fmaxf(v1, 0.f);
                    *(float2*)(C32 + base) = o;
                    if (MODE == 1) {
                        __half2 p = __floats2half2_rn(o.x, o.y);
                        *(uint32_t*)(C16 + base) = *(uint32_t*)&p;
                    }
                }
            }
        }
}

// ---------------- driver -----------------------------------------------------
extern "C" void kernel_launch(void* const* d_in, const int* in_sizes, int n_in,
                              void* d_out, int out_size)
{
    const float* V     = (const float*)d_in[0];
    const float* E     = (const float*)d_in[1];
    const int*   eidx  = (const int*)d_in[2];
    const int*   rev   = (const int*)d_in[3];
    const int*   batch = (const int*)d_in[4];
    const float* wgt   = (const float*)d_in[5];
    const float* W_i   = (const float*)d_in[6];
    const float* W_h   = (const float*)d_in[7];
    const float* W_o   = (const float*)d_in[8];
    const float* b_o   = (const float*)d_in[9];

    const int* src = eidx;
    const int* dst = eidx + NEDGE;
    float* out = (float*)d_out;

    float *h0, *agg;
    cudaGetSymbolAddress((void**)&h0,  g_h0);
    cudaGetSymbolAddress((void**)&agg, g_agg);
    unsigned short *h16, *mF, *WiF, *WhF, *WoF;
    cudaGetSymbolAddress((void**)&h16, g_h16);
    cudaGetSymbolAddress((void**)&mF,  g_mF);
    cudaGetSymbolAddress((void**)&WiF, g_WiF);
    cudaGetSymbolAddress((void**)&WhF, g_WhF);
    cudaGetSymbolAddress((void**)&WoF, g_WoF);

    cudaFuncSetAttribute(gemm_dense,  cudaFuncAttributeMaxDynamicSharedMemorySize, SMEM_GEMM);
    cudaFuncSetAttribute(gemm_mma<1>, cudaFuncAttributeMaxDynamicSharedMemorySize, SMEM_GEMM);
    cudaFuncSetAttribute(gemm_mma<3>, cudaFuncAttributeMaxDynamicSharedMemorySize, SMEM_GEMM);

    const dim3 blk(256);
    const dim3 grid_e(4, (NEDGE + 127) / 128);
    const dim3 grid_a(4, (NA    + 127) / 128);
    const int  aggN4    = (NA * HID) / 4;
    const int  zeroGrid = (aggN4 + 255) / 256;
    const int  ewGrid   = (NEDGE * 64 + 255) / 256;

    float* hOut = out + (size_t)NA * HID + NA;

    // 0) convert weights to fp16 (K-padded)
    cvtw_k<<<(512 * KP1 + 255) / 256, 256>>>(W_i, WiF, 512, KIN,  KP1);
    cvtw_k<<<(512 * KP2 + 255) / 256, 256>>>(W_h, WhF, 512, HID,  KP2);
    cvtw_k<<<(512 * KP3 + 255) / 256, 256>>>(W_o, WoF, 512, KOUT, KP3);

    // 1) h0 = relu([V[src];E] @ W_i^T)  -> fp32 h0 + fp16 h16
    gemm_mma<1><<<grid_e, blk, SMEM_GEMM>>>(WiF, V, E, src, nullptr, nullptr,
                                            h0, h16, NEDGE, KIN, KP1);

    // 2) three message-passing steps; fp16 h in flight; last also writes fp32 h
    for (int t = 0; t < 3; t++) {
        zero_k<<<zeroGrid, 256>>>((float4*)agg, aggN4);
        scatter_k<<<ewGrid, 256>>>(h16, dst, wgt, agg);
        msg_k<<<ewGrid, 256>>>(h16, src, rev, wgt, agg, mF);
        gemm_dense<<<grid_e, blk, SMEM_GEMM>>>(mF, WhF, h0,
                                               (t == 2) ? hOut : nullptr, h16);
    }

    // 3) final aggregation (unweighted) from fp16 h
    zero_k<<<zeroGrid, 256>>>((float4*)agg, aggN4);
    scatter_k<<<ewGrid, 256>>>(h16, dst, nullptr, agg);

    // 4) h_atom = relu([V;agg] @ W_o^T + b_o)
    gemm_mma<3><<<grid_a, blk, SMEM_GEMM>>>(WoF, V, nullptr, nullptr, agg, b_o,
                                            out, nullptr, NA, KOUT, KP3);

    // 5) atom_batch as float
    batch_k<<<(NA + 255) / 256, 256>>>(batch, out + (size_t)NA * HID);
}

// round 16
// speedup vs baseline: 1.2577x; 1.1092x over previous
#include <cuda_runtime.h>
#include <cuda_fp16.h>
#include <cstdint>

#define NA    100000
#define NEDGE 200000
#define HID   512
#define AD    133
#define BD    14
#define KIN   147   // AD + BD
#define KOUT  645   // AD + HID
#define KP1   160   // KIN padded to 32
#define KP2   512
#define KP3   672   // KOUT padded to 32
#define CK    32    // K chunk

// ---------------- scratch (static device globals; no allocation) ------------
__device__ float g_h0 [(size_t)NEDGE * HID];        // fp32 residual
__device__ float g_agg[(size_t)NA    * HID];
__device__ __align__(16) unsigned short g_h16[(size_t)NEDGE * HID];  // fp16 h
__device__ __align__(16) unsigned short g_mF [(size_t)NEDGE * HID];  // fp16 A operand (shared: prep1 / msg / prep3)
// fp16 weights, K-padded
__device__ __align__(16) unsigned short g_WiF[512 * KP1];
__device__ __align__(16) unsigned short g_WhF[512 * KP2];
__device__ __align__(16) unsigned short g_WoF[512 * KP3];

// ---------------- helpers ----------------------------------------------------
__device__ __forceinline__ uint32_t smem_u32(const void* p) {
    uint32_t a;
    asm("{ .reg .u64 t; cvta.to.shared.u64 t, %1; cvt.u32.u64 %0, t; }" : "=r"(a) : "l"(p));
    return a;
}
__device__ __forceinline__ void ldsm4(uint32_t* r, uint32_t addr) {
    asm volatile("ldmatrix.sync.aligned.m8n8.x4.shared.b16 {%0,%1,%2,%3}, [%4];"
                 : "=r"(r[0]), "=r"(r[1]), "=r"(r[2]), "=r"(r[3]) : "r"(addr));
}
__device__ __forceinline__ void mma16816(float* d, const uint32_t* a,
                                         uint32_t b0, uint32_t b1) {
    asm volatile(
        "mma.sync.aligned.m16n8k16.row.col.f32.f16.f16.f32 "
        "{%0,%1,%2,%3}, {%4,%5,%6,%7}, {%8,%9}, {%0,%1,%2,%3};"
        : "+f"(d[0]), "+f"(d[1]), "+f"(d[2]), "+f"(d[3])
        : "r"(a[0]), "r"(a[1]), "r"(a[2]), "r"(a[3]), "r"(b0), "r"(b1));
}
__device__ __forceinline__ void cp16(uint32_t dst, const void* src) {
    asm volatile("cp.async.ca.shared.global [%0], [%1], 16;" :: "r"(dst), "l"(src));
}
__device__ __forceinline__ void red4(float* p, float a, float b, float c, float d) {
    asm volatile("red.global.add.v4.f32 [%0], {%1,%2,%3,%4};"
                 :: "l"(p), "f"(a), "f"(b), "f"(c), "f"(d) : "memory");
}
// pack 8 fp32 -> 8 fp16 (RNE) in one uint4
__device__ __forceinline__ uint4 pack8h(const float* x) {
    uint4 r;
    __half2 p0 = __floats2half2_rn(x[0], x[1]);
    __half2 p1 = __floats2half2_rn(x[2], x[3]);
    __half2 p2 = __floats2half2_rn(x[4], x[5]);
    __half2 p3 = __floats2half2_rn(x[6], x[7]);
    r.x = *(uint32_t*)&p0; r.y = *(uint32_t*)&p1;
    r.z = *(uint32_t*)&p2; r.w = *(uint32_t*)&p3;
    return r;
}
__device__ __forceinline__ void unpack8h(uint4 v, float* x) {
    __half2* ph = (__half2*)&v;
#pragma unroll
    for (int i = 0; i < 4; i++) {
        float2 f = __half22float2(ph[i]);
        x[i * 2 + 0] = f.x;
        x[i * 2 + 1] = f.y;
    }
}

// ---------------- utility kernels ------------------------------------------
__global__ void cvtw_k(const float* __restrict__ W,
                       unsigned short* __restrict__ out,
                       int N, int K, int Kp) {
    int idx = blockIdx.x * blockDim.x + threadIdx.x;
    if (idx >= N * Kp) return;
    int n = idx / Kp, k = idx - n * Kp;
    float v = (k < K) ? W[(size_t)n * K + k] : 0.f;
    __half h = __float2half_rn(v);
    out[idx] = *(unsigned short*)&h;
}

__global__ void zero_k(float4* __restrict__ p, int n4) {
    int i = blockIdx.x * blockDim.x + threadIdx.x;
    if (i < n4) p[i] = make_float4(0.f, 0.f, 0.f, 0.f);
}

// agg[dst[e]] += w[e] * h16[e]
__global__ void scatter_k(const unsigned short* __restrict__ h16,
                          const int* __restrict__ dst,
                          const float* __restrict__ wgt,
                          float* __restrict__ agg) {
    int idx = blockIdx.x * blockDim.x + threadIdx.x;   // NEDGE * 64 threads
    if (idx >= NEDGE * 64) return;
    int e = idx >> 6;
    int c = (idx & 63) << 3;
    int d = dst[e];
    float w = wgt ? wgt[e] : 1.0f;
    uint4 hv = *(const uint4*)(h16 + (size_t)e * HID + c);
    float x[8];
    unpack8h(hv, x);
    float* a = agg + (size_t)d * HID + c;
    red4(a,     w * x[0], w * x[1], w * x[2], w * x[3]);
    red4(a + 4, w * x[4], w * x[5], w * x[6], w * x[7]);
}

// m_e = agg[src[e]] - wgt[rev[e]] * h16[rev[e]], fp16 out (stride HID)
__global__ void msg_k(const unsigned short* __restrict__ h16,
                      const int* __restrict__ src,
                      const int* __restrict__ rev,
                      const float* __restrict__ wgt,
                      const float* __restrict__ agg,
                      unsigned short* __restrict__ mF) {
    int idx = blockIdx.x * blockDim.x + threadIdx.x;   // NEDGE * 64 threads
    if (idx >= NEDGE * 64) return;
    int e = idx >> 6;
    int c = (idx & 63) << 3;
    int s = src[e];
    int r = rev[e];
    float w = wgt[r];
    const float* ap = agg + (size_t)s * HID + c;
    float4 a0 = *(const float4*)ap;
    float4 a1 = *(const float4*)(ap + 4);
    uint4 hv = *(const uint4*)(h16 + (size_t)r * HID + c);
    float h[8];
    unpack8h(hv, h);
    float x[8] = { a0.x - w * h[0], a0.y - w * h[1], a0.z - w * h[2], a0.w - w * h[3],
                   a1.x - w * h[4], a1.y - w * h[5], a1.z - w * h[6], a1.w - w * h[7] };
    *(uint4*)(mF + (size_t)e * HID + c) = pack8h(x);
}

// prep1: A row e = [V[src[e]] ; E[e]] -> fp16, stride KP1
__global__ void prep1_k(const float* __restrict__ V,
                        const float* __restrict__ E,
                        const int* __restrict__ src,
                        unsigned short* __restrict__ out) {
    int idx = blockIdx.x * blockDim.x + threadIdx.x;   // NEDGE * (KP1/8)
    if (idx >= NEDGE * (KP1 / 8)) return;
    int e = idx / (KP1 / 8);
    int q = idx - e * (KP1 / 8);
    int k0 = q * 8;
    int s = src[e];
    float x[8];
#pragma unroll
    for (int i = 0; i < 8; i++) {
        int kk = k0 + i;
        float v = 0.f;
        if (kk < AD)       v = V[(size_t)s * AD + kk];
        else if (kk < KIN) v = E[(size_t)e * BD + (kk - AD)];
        x[i] = v;
    }
    *(uint4*)(out + (size_t)e * KP1 + k0) = pack8h(x);
}

// prep3: A row i = [V[i] ; agg[i]] -> fp16, stride KP3
__global__ void prep3_k(const float* __restrict__ V,
                        const float* __restrict__ agg,
                        unsigned short* __restrict__ out) {
    int idx = blockIdx.x * blockDim.x + threadIdx.x;   // NA * (KP3/8)
    if (idx >= NA * (KP3 / 8)) return;
    int n = idx / (KP3 / 8);
    int q = idx - n * (KP3 / 8);
    int k0 = q * 8;
    float x[8];
#pragma unroll
    for (int i = 0; i < 8; i++) {
        int kk = k0 + i;
        float v = 0.f;
        if (kk < AD)        v = V[(size_t)n * AD + kk];
        else if (kk < KOUT) v = agg[(size_t)n * HID + (kk - AD)];
        x[i] = v;
    }
    *(uint4*)(out + (size_t)n * KP3 + k0) = pack8h(x);
}

__global__ void batch_k(const int* __restrict__ b, float* __restrict__ out) {
    int i = blockIdx.x * blockDim.x + threadIdx.x;
    if (i < NA) out[i] = (float)b[i];
}

#define SW(o) ((o) ^ (((o) >> 3) & 0x70))

// ---------------- unified dense fp16 GEMM ------------------------------------
// C[M,512] = relu( A @ W^T (+ h0) (+ bias) ); C32 and/or C16 outputs.
// A: fp16 [M, Kp] dense.  CTA 128x128, CK=32, 2-stage, 256 thr, 2 CTAs/SM,
// warp tile 64x32.  Bounds-guarded (load clamp + store guard).
#define SMEM_GEMM 65536

__global__ __launch_bounds__(256, 2)
void gemm_dense(const unsigned short* __restrict__ AF,
                const unsigned short* __restrict__ WF,
                const float* __restrict__ h0,
                const float* __restrict__ bias,
                float* __restrict__ C32,
                unsigned short* __restrict__ C16,
                int M, int Kp)
{
    extern __shared__ __align__(1024) char sm[];
    const uint32_t sb = smem_u32(sm);
    const int tid   = threadIdx.x;
    const int lane  = tid & 31;
    const int warp  = tid >> 5;
    const int warpM = warp >> 2;
    const int warpN = warp & 3;

    const int jb = blockIdx.x * 128;
    const int mb = blockIdx.y * 128;

    const int arow = tid >> 1;
    const int aq   = tid & 1;
    int arow_c = mb + arow;                 // clamped load row
    if (arow_c >= M) arow_c = M - 1;

    float acc[4][4][4];
#pragma unroll
    for (int i = 0; i < 4; i++)
#pragma unroll
        for (int n = 0; n < 4; n++)
#pragma unroll
            for (int k = 0; k < 4; k++) acc[i][n][k] = 0.f;

#define CPT(kb, base) do {                                                      \
    const unsigned short* aF = AF + (size_t)arow_c * Kp + (kb) + aq * 16;       \
    const unsigned short* wF = WF + (size_t)(jb + arow) * Kp + (kb) + aq * 16;  \
    int o = arow * 128 + aq * 32;                                               \
    cp16(sb + (base) + SW(o),      aF);                                         \
    cp16(sb + (base) + SW(o + 16), aF + 8);                                     \
    cp16(sb + (base) + 16384 + SW(o),      wF);                                 \
    cp16(sb + (base) + 16384 + SW(o + 16), wF + 8);                             \
    asm volatile("cp.async.commit_group;" ::: "memory");                        \
} while (0)

#define DOMMA(base) do {                                                        \
    _Pragma("unroll")                                                           \
    for (int s = 0; s < 2; s++) {                                               \
        const int cb = s * 32 + ((lane >> 4) << 4);                             \
        uint32_t Bf[2][4];                                                      \
        _Pragma("unroll")                                                       \
        for (int j = 0; j < 2; j++) {                                           \
            int r = warpN * 32 + j * 16 + (lane & 15);                          \
            ldsm4(Bf[j], sb + (base) + 16384 + SW(r * 128 + cb));               \
        }                                                                       \
        _Pragma("unroll")                                                       \
        for (int i = 0; i < 4; i++) {                                           \
            uint32_t Af[4];                                                     \
            int r = warpM * 64 + i * 16 + (lane & 15);                          \
            ldsm4(Af, sb + (base) + SW(r * 128 + cb));                          \
            _Pragma("unroll")                                                   \
            for (int nt = 0; nt < 4; nt++) {                                    \
                int j = nt >> 1, sel = nt & 1;                                  \
                mma16816(acc[i][nt], Af, Bf[j][sel], Bf[j][sel + 2]);           \
            }                                                                   \
        }                                                                       \
    }                                                                           \
} while (0)

    const int nc = Kp / CK;
    CPT(0, 0);
    asm volatile("cp.async.wait_group 0;" ::: "memory");
    __syncthreads();
    for (int t = 0; t < nc; t++) {
        const int base  = (t & 1) * 32768;
        const int obase = 32768 - base;
        const bool nxt = (t + 1 < nc);
        if (nxt) CPT((t + 1) * CK, obase);
        DOMMA(base);
        if (nxt) {
            asm volatile("cp.async.wait_group 0;" ::: "memory");
            __syncthreads();
        }
    }
#undef CPT
#undef DOMMA

    // epilogue: (+h0) (+bias), relu -> C32 / C16 (guarded)
#pragma unroll
    for (int i = 0; i < 4; i++)
#pragma unroll
        for (int nt = 0; nt < 4; nt++) {
            const int r0 = mb + warpM * 64 + i * 16 + (lane >> 2);
            const int c  = jb + warpN * 32 + nt * 8 + (lane & 3) * 2;
#pragma unroll
            for (int hh2 = 0; hh2 < 2; hh2++) {
                const int r = r0 + hh2 * 8;
                if (r < M) {
                    float v0 = acc[i][nt][hh2 * 2 + 0];
                    float v1 = acc[i][nt][hh2 * 2 + 1];
                    const size_t base = (size_t)r * HID + c;
                    if (h0) {
                        float2 a = *(const float2*)(h0 + base);
                        v0 += a.x; v1 += a.y;
                    }
                    if (bias) { v0 += bias[c]; v1 += bias[c + 1]; }
                    float2 o;
                    o.x = fmaxf(v0, 0.f);
                    o.y = fmaxf(v1, 0.f);
                    if (C32) *(float2*)(C32 + base) = o;
                    if (C16) {
                        __half2 p = __floats2half2_rn(o.x, o.y);
                        *(uint32_t*)(C16 + base) = *(uint32_t*)&p;
                    }
                }
            }
        }
}

// ---------------- driver -----------------------------------------------------
extern "C" void kernel_launch(void* const* d_in, const int* in_sizes, int n_in,
                              void* d_out, int out_size)
{
    const float* V     = (const float*)d_in[0];
    const float* E     = (const float*)d_in[1];
    const int*   eidx  = (const int*)d_in[2];
    const int*   rev   = (const int*)d_in[3];
    const int*   batch = (const int*)d_in[4];
    const float* wgt   = (const float*)d_in[5];
    const float* W_i   = (const float*)d_in[6];
    const float* W_h   = (const float*)d_in[7];
    const float* W_o   = (const float*)d_in[8];
    const float* b_o   = (const float*)d_in[9];

    const int* src = eidx;
    const int* dst = eidx + NEDGE;
    float* out = (float*)d_out;

    float *h0, *agg;
    cudaGetSymbolAddress((void**)&h0,  g_h0);
    cudaGetSymbolAddress((void**)&agg, g_agg);
    unsigned short *h16, *mF, *WiF, *WhF, *WoF;
    cudaGetSymbolAddress((void**)&h16, g_h16);
    cudaGetSymbolAddress((void**)&mF,  g_mF);
    cudaGetSymbolAddress((void**)&WiF, g_WiF);
    cudaGetSymbolAddress((void**)&WhF, g_WhF);
    cudaGetSymbolAddress((void**)&WoF, g_WoF);

    cudaFuncSetAttribute(gemm_dense, cudaFuncAttributeMaxDynamicSharedMemorySize, SMEM_GEMM);

    const dim3 blk(256);
    const dim3 grid_e(4, (NEDGE + 127) / 128);   // 4 x 1563
    const dim3 grid_a(4, (NA    + 127) / 128);   // 4 x 782
    const int  aggN4    = (NA * HID) / 4;
    const int  zeroGrid = (aggN4 + 255) / 256;
    const int  ewGrid   = (NEDGE * 64 + 255) / 256;
    const int  p1Grid   = (NEDGE * (KP1 / 8) + 255) / 256;
    const int  p3Grid   = (NA    * (KP3 / 8) + 255) / 256;

    float* hOut = out + (size_t)NA * HID + NA;

    // 0) convert weights to fp16 (K-padded)
    cvtw_k<<<(512 * KP1 + 255) / 256, 256>>>(W_i, WiF, 512, KIN,  KP1);
    cvtw_k<<<(512 * KP2 + 255) / 256, 256>>>(W_h, WhF, 512, HID,  KP2);
    cvtw_k<<<(512 * KP3 + 255) / 256, 256>>>(W_o, WoF, 512, KOUT, KP3);

    // 1) h0 = relu([V[src];E] @ W_i^T)  (prep + dense)
    prep1_k<<<p1Grid, 256>>>(V, E, src, mF);
    gemm_dense<<<grid_e, blk, SMEM_GEMM>>>(mF, WiF, nullptr, nullptr,
                                           h0, h16, NEDGE, KP1);

    // 2) three message-passing steps; fp16 h in flight; last also writes fp32 h
    for (int t = 0; t < 3; t++) {
        zero_k<<<zeroGrid, 256>>>((float4*)agg, aggN4);
        scatter_k<<<ewGrid, 256>>>(h16, dst, wgt, agg);
        msg_k<<<ewGrid, 256>>>(h16, src, rev, wgt, agg, mF);
        gemm_dense<<<grid_e, blk, SMEM_GEMM>>>(mF, WhF, h0, nullptr,
                                               (t == 2) ? hOut : nullptr, h16,
                                               NEDGE, KP2);
    }

    // 3) final aggregation (unweighted) from fp16 h
    zero_k<<<zeroGrid, 256>>>((float4*)agg, aggN4);
    scatter_k<<<ewGrid, 256>>>(h16, dst, nullptr, agg);

    // 4) h_atom = relu([V;agg] @ W_o^T + b_o)  (prep + dense)
    prep3_k<<<p3Grid, 256>>>(V, agg, mF);
    gemm_dense<<<grid_a, blk, SMEM_GEMM>>>(mF, WoF, nullptr, b_o,
                                           out, nullptr, NA, KP3);

    // 5) atom_batch as float
    batch_k<<<(NA + 255) / 256, 256>>>(batch, out + (size_t)NA * HID);
}